// round 15
// baseline (speedup 1.0000x reference)
#include <cuda_runtime.h>
#include <math.h>
#include <stdint.h>

#define NEG_K 32
#define TEMP 0.07f
#define INV_T (1.0f / 0.07f)

#define H_FIX 768
#define ROW_BYTES (H_FIX * 4)                 // 3072
#define NSTREAMS (NEG_K + 1)                  // 33
#define FAN_BYTES (NSTREAMS * ROW_BYTES)      // 101376

// Self-resetting cross-block accumulator (zero-initialized; reset each launch).
__device__ float g_sum;
__device__ int   g_count;

__device__ __forceinline__ uint32_t smem_u32(const void* p) {
    return (uint32_t)__cvta_generic_to_shared(p);
}
__device__ __forceinline__ void mbar_init(uint32_t addr, uint32_t cnt) {
    asm volatile("mbarrier.init.shared::cta.b64 [%0], %1;" :: "r"(addr), "r"(cnt) : "memory");
}
__device__ __forceinline__ void mbar_expect_tx(uint32_t addr, uint32_t bytes) {
    asm volatile("mbarrier.arrive.expect_tx.shared::cta.b64 _, [%0], %1;"
                 :: "r"(addr), "r"(bytes) : "memory");
}
__device__ __forceinline__ void bulk_cp(uint32_t dst, const void* src, uint32_t bytes, uint32_t mbar) {
    asm volatile("cp.async.bulk.shared::cta.global.mbarrier::complete_tx::bytes [%0], [%1], %2, [%3];"
                 :: "r"(dst), "l"(src), "r"(bytes), "r"(mbar) : "memory");
}
__device__ __forceinline__ void mbar_wait(uint32_t addr, uint32_t parity) {
    asm volatile(
        "{\n\t.reg .pred P;\n"
        "W_%=:\n\t"
        "mbarrier.try_wait.parity.acquire.cta.shared::cta.b64 P, [%0], %1, 0x989680;\n\t"
        "@P bra D_%=;\n\t"
        "bra W_%=;\n"
        "D_%=:\n\t}"
        :: "r"(addr), "r"(parity) : "memory");
}

// ---------------- full-fanout bulk kernel (H == 768) ----------------
__global__ __launch_bounds__(192) void infonce_fan_kernel(
    const float* __restrict__ hs,       // [B, S, H]
    const int*   __restrict__ selection,// [B]
    const int*   __restrict__ mask,     // [B, S]
    const float* __restrict__ noise,    // [loss_size, NEG_K]
    float* __restrict__ out,            // [1]
    int B, int S, int valid, int loss_size)
{
    extern __shared__ __align__(128) float rows[];   // [NSTREAMS][H_FIX]

    const int l    = blockIdx.x;
    const int tid  = threadIdx.x;
    const int lane = tid & 31;
    const int warp = tid >> 5;          // 0..5

    __shared__ float logits_s[NSTREAMS];
    __shared__ __align__(8) unsigned long long mbar_store;
    const uint32_t mb = smem_u32(&mbar_store);

    const int sel = __ldg(selection + l);   // first load

    // Anchor -> registers (all warps, lane-sliced; overlaps the mask/cand trip)
    const float4* a4 = (const float4*)(hs + ((size_t)l * S + sel) * H_FIX);
    float4 areg[6];
    #pragma unroll
    for (int i = 0; i < 6; i++) areg[i] = __ldg(a4 + lane + 32 * i);

    if (tid == 0) mbar_init(mb, 1);
    __syncthreads();   // mbar init visible before anyone polls

    // Warp 0: noise + mask-sum -> cand (in registers) -> issue ALL 33 copies.
    if (warp == 0) {
        float nz = __ldg(noise + (size_t)l * NEG_K + lane);
        int msum = 0;
        const int* mrow = mask + (size_t)l * S;
        #pragma unroll 8
        for (int s = lane; s < S; s += 32) msum += mrow[s];
        #pragma unroll
        for (int o = 16; o; o >>= 1) msum += __shfl_xor_sync(0xffffffffu, msum, o);
        const int len_l = msum;
        const bool sir = (sel >= 1) && (sel <= len_l - 1);
        const int n_valid = sir ? (len_l - 2) : (len_l - 1);
        int cand = (int)floorf(nz * (float)n_valid) + 1;   // lane k -> cand[k]
        if (sir && cand >= sel) cand += 1;

        // lane k (1..31) issues stream j=k (uses cand[k-1]);
        // lane 0 issues j=0 (positive) and j=32 (cand[31]).
        const int cprev = __shfl_up_sync(0xffffffffu, cand, 1);   // cand[lane-1]
        const int c31   = __shfl_sync(0xffffffffu, cand, 31);     // cand[31]

        if (lane == 0) mbar_expect_tx(mb, (uint32_t)NSTREAMS * ROW_BYTES);
        __syncwarp();   // expect_tx strictly before any complete_tx can land

        if (lane == 0) {
            bulk_cp(smem_u32(&rows[0]),
                    hs + ((size_t)(valid + l) * S + sel) * H_FIX, ROW_BYTES, mb);
            bulk_cp(smem_u32(&rows[32 * H_FIX]),
                    hs + ((size_t)l * S + c31) * H_FIX, ROW_BYTES, mb);
        } else {
            bulk_cp(smem_u32(&rows[lane * H_FIX]),
                    hs + ((size_t)l * S + cprev) * H_FIX, ROW_BYTES, mb);
        }
    }

    // Everyone: single wait for the whole 99 KB epoch.
    mbar_wait(mb, 0);

    // Compute: warp w owns streams j = w, w+6, w+12, ... (<= 32)
    #pragma unroll
    for (int k = 0; k < 6; k++) {
        const int j = warp + 6 * k;
        if (j < NSTREAMS) {
            const float4* v4 = (const float4*)&rows[j * H_FIX];
            float acc = 0.0f;
            #pragma unroll
            for (int i = 0; i < 6; i++) {
                float4 a = areg[i];
                float4 b = v4[lane + 32 * i];
                acc += a.x*b.x + a.y*b.y + a.z*b.z + a.w*b.w;
            }
            #pragma unroll
            for (int o = 16; o; o >>= 1) acc += __shfl_xor_sync(0xffffffffu, acc, o);
            if (lane == 0) logits_s[j] = acc;
        }
    }
    __syncthreads();

    // Warp 0: parallel logsumexp over 33 logits + grid reduction.
    if (warp == 0) {
        float v = logits_s[lane] * INV_T;
        float e = logits_s[NEG_K] * INV_T;
        float m = (lane == 0) ? fmaxf(v, e) : v;
        #pragma unroll
        for (int o = 16; o; o >>= 1) m = fmaxf(m, __shfl_xor_sync(0xffffffffu, m, o));
        float sse = __expf(v - m);
        if (lane == 0) sse += __expf(e - m);
        #pragma unroll
        for (int o = 16; o; o >>= 1) sse += __shfl_xor_sync(0xffffffffu, sse, o);

        if (lane == 0) {
            float rowloss = (m + logf(sse)) - logits_s[0] * INV_T;
            atomicAdd(&g_sum, rowloss);
            __threadfence();
            int done = atomicAdd(&g_count, 1);
            if (done == loss_size - 1) {
                float total = atomicExch(&g_sum, 0.0f);   // reset for graph replay
                g_count = 0;
                out[0] = (total + (float)valid * logf((float)(NEG_K + 1))) / (float)B;
            }
        }
    }
}

// ---------------- generic fallback (any H), LDG-based ----------------
__global__ __launch_bounds__(256) void infonce_generic_kernel(
    const float* __restrict__ hs, const int* __restrict__ selection,
    const int* __restrict__ mask, const float* __restrict__ noise,
    float* __restrict__ out, int B, int S, int H, int valid, int loss_size)
{
    const int l    = blockIdx.x;
    const int tid  = threadIdx.x;
    const int lane = tid & 31;
    const int warp = tid >> 5;

    __shared__ float logits_s[NSTREAMS];
    __shared__ int   cand_s[NEG_K];

    const int sel = __ldg(selection + l);
    if (warp == 0) {
        float nz = __ldg(noise + (size_t)l * NEG_K + lane);
        int msum = 0;
        const int* mrow = mask + (size_t)l * S;
        for (int s = lane; s < S; s += 32) msum += mrow[s];
        #pragma unroll
        for (int o = 16; o; o >>= 1) msum += __shfl_xor_sync(0xffffffffu, msum, o);
        const int len_l = msum;
        const bool sir = (sel >= 1) && (sel <= len_l - 1);
        const int n_valid = sir ? (len_l - 2) : (len_l - 1);
        int cand = (int)floorf(nz * (float)n_valid) + 1;
        if (sir && cand >= sel) cand += 1;
        cand_s[lane] = cand;
    }
    __syncthreads();

    const float* a = hs + ((size_t)l * S + sel) * H;
    for (int j = warp; j <= NEG_K; j += blockDim.x >> 5) {
        const float* v = (j == 0)
            ? hs + ((size_t)(valid + l) * S + sel) * H
            : hs + ((size_t)l * S + cand_s[j - 1]) * H;
        float acc = 0.0f;
        for (int i = lane; i < H; i += 32) acc += a[i] * v[i];
        #pragma unroll
        for (int o = 16; o; o >>= 1) acc += __shfl_xor_sync(0xffffffffu, acc, o);
        if (lane == 0) logits_s[j] = acc;
    }
    __syncthreads();

    if (tid == 0) {
        float m = -INFINITY;
        for (int j = 0; j <= NEG_K; j++) m = fmaxf(m, logits_s[j] * INV_T);
        float sse = 0.0f;
        for (int j = 0; j <= NEG_K; j++) sse += __expf(logits_s[j] * INV_T - m);
        float rowloss = (m + logf(sse)) - logits_s[0] * INV_T;
        atomicAdd(&g_sum, rowloss);
        __threadfence();
        int done = atomicAdd(&g_count, 1);
        if (done == loss_size - 1) {
            float total = atomicExch(&g_sum, 0.0f);
            g_count = 0;
            out[0] = (total + (float)valid * logf((float)(NEG_K + 1))) / (float)B;
        }
    }
}

extern "C" void kernel_launch(void* const* d_in, const int* in_sizes, int n_in,
                              void* d_out, int out_size) {
    const float* hs        = (const float*)d_in[0]; // [B,S,H]
    const int*   selection = (const int*)  d_in[1]; // [B]
    const int*   mask      = (const int*)  d_in[2]; // [B,S]
    const float* noise     = (const float*)d_in[3]; // [loss_size, NEG_K]
    float*       out       = (float*)d_out;

    const int B = in_sizes[1];
    const int S = in_sizes[2] / B;
    const int H = in_sizes[0] / (B * S);
    const int loss_size = in_sizes[3] / NEG_K;      // from noise shape (host-side)
    const int valid = B - loss_size;

    if (H == H_FIX) {
        cudaFuncSetAttribute(infonce_fan_kernel,
                             cudaFuncAttributeMaxDynamicSharedMemorySize, FAN_BYTES);
        infonce_fan_kernel<<<loss_size, 192, FAN_BYTES>>>(hs, selection, mask, noise, out,
                                                          B, S, valid, loss_size);
    } else {
        infonce_generic_kernel<<<loss_size, 256>>>(hs, selection, mask, noise, out,
                                                   B, S, H, valid, loss_size);
    }
}

// round 16
// speedup vs baseline: 1.2604x; 1.2604x over previous
#include <cuda_runtime.h>
#include <math.h>
#include <stdint.h>

#define NEG_K 32
#define TEMP 0.07f
#define INV_T (1.0f / 0.07f)

#define H_FIX 768
#define ROW_BYTES (H_FIX * 4)            // 3072
#define NSTREAMS (NEG_K + 1)             // 33
#define NLINES (ROW_BYTES / 128)         // 24 lines of 128B per row
#define TOTLINES (NSTREAMS * NLINES)     // 792

// Self-resetting cross-block accumulator (zero-initialized; reset each launch).
__device__ float g_sum;
__device__ int   g_count;

// ---------------- prefetch-then-consume kernel (H == 768) ----------------
__global__ __launch_bounds__(192) void infonce_pf_kernel(
    const float* __restrict__ hs,       // [B, S, H]
    const int*   __restrict__ selection,// [B]
    const int*   __restrict__ mask,     // [B, S]
    const float* __restrict__ noise,    // [loss_size, NEG_K]
    float* __restrict__ out,            // [1]
    int B, int S, int valid, int loss_size)
{
    const int l    = blockIdx.x;
    const int tid  = threadIdx.x;
    const int lane = tid & 31;
    const int warp = tid >> 5;          // 0..5

    __shared__ const float* ptr_s[NSTREAMS];   // row base pointers, j = 0..32
    __shared__ float logits_s[NSTREAMS];

    const int sel = __ldg(selection + l);   // first load

    // Anchor -> registers (lane-sliced; overlaps the mask/cand trip below)
    const float4* a4 = (const float4*)(hs + ((size_t)l * S + sel) * H_FIX);
    float4 areg[6];
    #pragma unroll
    for (int i = 0; i < 6; i++) areg[i] = __ldg(a4 + lane + 32 * i);

    // Warp 0: noise + mask-sum -> cand -> row-pointer table
    if (warp == 0) {
        float nz = __ldg(noise + (size_t)l * NEG_K + lane);
        int msum = 0;
        const int* mrow = mask + (size_t)l * S;
        #pragma unroll 8
        for (int s = lane; s < S; s += 32) msum += mrow[s];
        #pragma unroll
        for (int o = 16; o; o >>= 1) msum += __shfl_xor_sync(0xffffffffu, msum, o);
        const int len_l = msum;
        const bool sir = (sel >= 1) && (sel <= len_l - 1);
        const int n_valid = sir ? (len_l - 2) : (len_l - 1);
        int cand = (int)floorf(nz * (float)n_valid) + 1;   // lane k -> cand[k]
        if (sir && cand >= sel) cand += 1;

        ptr_s[lane + 1] = hs + ((size_t)l * S + cand) * H_FIX;          // j = 1..32
        if (lane == 0)
            ptr_s[0] = hs + ((size_t)(valid + l) * S + sel) * H_FIX;    // positive
    }
    __syncthreads();

    // Prefetch the ENTIRE 99 KB row set into L2 — zero smem, zero regs,
    // unbounded MLP. 792 lines / 192 threads ≈ 4 insts each, j ascending
    // so the first-consumed rows are demanded first.
    #pragma unroll
    for (int idx = tid; idx < TOTLINES; idx += 192) {
        const char* p = (const char*)ptr_s[idx / NLINES] + (size_t)(idx % NLINES) * 128;
        asm volatile("prefetch.global.L2 [%0];" :: "l"(p));
    }

    // Consume: warp w owns dots j = w + 6k; processed in pairs (2 LDG streams).
    #pragma unroll
    for (int k = 0; k < 6; k += 2) {
        const int j0 = warp + 6 * k;
        const int j1 = warp + 6 * (k + 1);
        if (j0 >= NSTREAMS) break;
        const bool h1 = (j1 < NSTREAMS);
        const float4* p0 = (const float4*)ptr_s[j0];
        const float4* p1 = h1 ? (const float4*)ptr_s[j1] : p0;
        float acc0 = 0.0f, acc1 = 0.0f;
        #pragma unroll
        for (int i = 0; i < 6; i++) {
            float4 a  = areg[i];
            float4 b0 = __ldg(p0 + lane + 32 * i);
            float4 b1 = __ldg(p1 + lane + 32 * i);
            acc0 += a.x*b0.x + a.y*b0.y + a.z*b0.z + a.w*b0.w;
            acc1 += a.x*b1.x + a.y*b1.y + a.z*b1.z + a.w*b1.w;
        }
        #pragma unroll
        for (int o = 16; o; o >>= 1) {
            acc0 += __shfl_xor_sync(0xffffffffu, acc0, o);
            acc1 += __shfl_xor_sync(0xffffffffu, acc1, o);
        }
        if (lane == 0) {
            logits_s[j0] = acc0;
            if (h1) logits_s[j1] = acc1;
        }
    }
    __syncthreads();

    // Warp 0: parallel logsumexp over 33 logits + grid reduction.
    if (warp == 0) {
        float v = logits_s[lane] * INV_T;
        float e = logits_s[NEG_K] * INV_T;
        float m = (lane == 0) ? fmaxf(v, e) : v;
        #pragma unroll
        for (int o = 16; o; o >>= 1) m = fmaxf(m, __shfl_xor_sync(0xffffffffu, m, o));
        float sse = __expf(v - m);
        if (lane == 0) sse += __expf(e - m);
        #pragma unroll
        for (int o = 16; o; o >>= 1) sse += __shfl_xor_sync(0xffffffffu, sse, o);

        if (lane == 0) {
            float rowloss = (m + logf(sse)) - logits_s[0] * INV_T;
            atomicAdd(&g_sum, rowloss);
            __threadfence();
            int done = atomicAdd(&g_count, 1);
            if (done == loss_size - 1) {
                float total = atomicExch(&g_sum, 0.0f);   // reset for graph replay
                g_count = 0;
                out[0] = (total + (float)valid * logf((float)(NEG_K + 1))) / (float)B;
            }
        }
    }
}

// ---------------- generic fallback (any H), LDG-based ----------------
__global__ __launch_bounds__(256) void infonce_generic_kernel(
    const float* __restrict__ hs, const int* __restrict__ selection,
    const int* __restrict__ mask, const float* __restrict__ noise,
    float* __restrict__ out, int B, int S, int H, int valid, int loss_size)
{
    const int l    = blockIdx.x;
    const int tid  = threadIdx.x;
    const int lane = tid & 31;
    const int warp = tid >> 5;

    __shared__ float logits_s[NSTREAMS];
    __shared__ int   cand_s[NEG_K];

    const int sel = __ldg(selection + l);
    if (warp == 0) {
        float nz = __ldg(noise + (size_t)l * NEG_K + lane);
        int msum = 0;
        const int* mrow = mask + (size_t)l * S;
        for (int s = lane; s < S; s += 32) msum += mrow[s];
        #pragma unroll
        for (int o = 16; o; o >>= 1) msum += __shfl_xor_sync(0xffffffffu, msum, o);
        const int len_l = msum;
        const bool sir = (sel >= 1) && (sel <= len_l - 1);
        const int n_valid = sir ? (len_l - 2) : (len_l - 1);
        int cand = (int)floorf(nz * (float)n_valid) + 1;
        if (sir && cand >= sel) cand += 1;
        cand_s[lane] = cand;
    }
    __syncthreads();

    const float* a = hs + ((size_t)l * S + sel) * H;
    for (int j = warp; j <= NEG_K; j += blockDim.x >> 5) {
        const float* v = (j == 0)
            ? hs + ((size_t)(valid + l) * S + sel) * H
            : hs + ((size_t)l * S + cand_s[j - 1]) * H;
        float acc = 0.0f;
        for (int i = lane; i < H; i += 32) acc += a[i] * v[i];
        #pragma unroll
        for (int o = 16; o; o >>= 1) acc += __shfl_xor_sync(0xffffffffu, acc, o);
        if (lane == 0) logits_s[j] = acc;
    }
    __syncthreads();

    if (tid == 0) {
        float m = -INFINITY;
        for (int j = 0; j <= NEG_K; j++) m = fmaxf(m, logits_s[j] * INV_T);
        float sse = 0.0f;
        for (int j = 0; j <= NEG_K; j++) sse += __expf(logits_s[j] * INV_T - m);
        float rowloss = (m + logf(sse)) - logits_s[0] * INV_T;
        atomicAdd(&g_sum, rowloss);
        __threadfence();
        int done = atomicAdd(&g_count, 1);
        if (done == loss_size - 1) {
            float total = atomicExch(&g_sum, 0.0f);
            g_count = 0;
            out[0] = (total + (float)valid * logf((float)(NEG_K + 1))) / (float)B;
        }
    }
}

extern "C" void kernel_launch(void* const* d_in, const int* in_sizes, int n_in,
                              void* d_out, int out_size) {
    const float* hs        = (const float*)d_in[0]; // [B,S,H]
    const int*   selection = (const int*)  d_in[1]; // [B]
    const int*   mask      = (const int*)  d_in[2]; // [B,S]
    const float* noise     = (const float*)d_in[3]; // [loss_size, NEG_K]
    float*       out       = (float*)d_out;

    const int B = in_sizes[1];
    const int S = in_sizes[2] / B;
    const int H = in_sizes[0] / (B * S);
    const int loss_size = in_sizes[3] / NEG_K;      // from noise shape (host-side)
    const int valid = B - loss_size;

    if (H == H_FIX) {
        infonce_pf_kernel<<<loss_size, 192>>>(hs, selection, mask, noise, out,
                                              B, S, valid, loss_size);
    } else {
        infonce_generic_kernel<<<loss_size, 256>>>(hs, selection, mask, noise, out,
                                                   B, S, H, valid, loss_size);
    }
}

// round 17
// speedup vs baseline: 1.4055x; 1.1151x over previous
#include <cuda_runtime.h>
#include <math.h>
#include <stdint.h>

#define NEG_K 32
#define TEMP 0.07f
#define INV_T (1.0f / 0.07f)

#define H_FIX 768
#define ROW_BYTES (H_FIX * 4)            // 3072
#define NSTREAMS (NEG_K + 1)             // 33
#define NLINES (ROW_BYTES / 128)         // 24 x 128B lines per row
#define TOTLINES (NSTREAMS * NLINES)     // 792
#define NTHREADS 384

// Self-resetting cross-block accumulator (zero-initialized; reset each launch).
__device__ float g_sum;
__device__ int   g_count;

// ---------------- high-occupancy prefetch+consume kernel (H == 768) ----------------
__global__ __launch_bounds__(NTHREADS, 4) void infonce_occ_kernel(
    const float* __restrict__ hs,       // [B, S, H]
    const int*   __restrict__ selection,// [B]
    const int*   __restrict__ mask,     // [B, S]
    const float* __restrict__ noise,    // [loss_size, NEG_K]
    float* __restrict__ out,            // [1]
    int B, int S, int valid, int loss_size)
{
    const int l    = blockIdx.x;
    const int tid  = threadIdx.x;
    const int lane = tid & 31;
    const int warp = tid >> 5;          // 0..11

    __shared__ __align__(16) float anchor_s[H_FIX];      // 3 KB
    __shared__ const float* ptr_s[NSTREAMS];
    __shared__ float logits_s[NSTREAMS];

    const int sel = __ldg(selection + l);   // first load (uniform)

    if (warp == 0) {
        // noise + mask-sum -> cand -> row-pointer table (one parallel trip)
        float nz = __ldg(noise + (size_t)l * NEG_K + lane);
        int msum = 0;
        const int* mrow = mask + (size_t)l * S;
        #pragma unroll 8
        for (int s = lane; s < S; s += 32) msum += mrow[s];
        #pragma unroll
        for (int o = 16; o; o >>= 1) msum += __shfl_xor_sync(0xffffffffu, msum, o);
        const int len_l = msum;
        const bool sir = (sel >= 1) && (sel <= len_l - 1);
        const int n_valid = sir ? (len_l - 2) : (len_l - 1);
        int cand = (int)floorf(nz * (float)n_valid) + 1;   // lane k -> cand[k]
        if (sir && cand >= sel) cand += 1;

        ptr_s[lane + 1] = hs + ((size_t)l * S + cand) * H_FIX;          // j = 1..32
        if (lane == 0)
            ptr_s[0] = hs + ((size_t)(valid + l) * S + sel) * H_FIX;    // positive
    } else {
        // warps 1..11: stage anchor gmem -> smem (192 float4; threads 32..223)
        const float4* a4g = (const float4*)(hs + ((size_t)l * S + sel) * H_FIX);
        const int i = tid - 32;
        if (i < H_FIX / 4) ((float4*)anchor_s)[i] = __ldg(a4g + i);
    }
    __syncthreads();

    // Prefetch the full 99 KB row set into L2 (no regs, no smem, max MLP).
    #pragma unroll
    for (int idx = tid; idx < TOTLINES; idx += NTHREADS) {
        const char* p = (const char*)ptr_s[idx / NLINES] + (size_t)(idx % NLINES) * 128;
        asm volatile("prefetch.global.L2 [%0];" :: "l"(p));
    }

    // Consume: warp w owns j = w, w+12, w+24 (3 concurrent LDG streams).
    {
        const int j0 = warp;
        const int j1 = warp + 12;
        const int j2 = warp + 24;
        const bool h2 = (j2 < NSTREAMS);     // warps 0..8
        const float4* p0 = (const float4*)ptr_s[j0];
        const float4* p1 = (const float4*)ptr_s[j1];
        const float4* p2 = h2 ? (const float4*)ptr_s[j2] : p0;
        const float4* a4s = (const float4*)anchor_s;

        float acc0 = 0.0f, acc1 = 0.0f, acc2 = 0.0f;
        #pragma unroll
        for (int i = 0; i < 6; i++) {
            const int idx = lane + 32 * i;
            float4 a  = a4s[idx];
            float4 b0 = __ldg(p0 + idx);
            float4 b1 = __ldg(p1 + idx);
            float4 b2 = __ldg(p2 + idx);
            acc0 += a.x*b0.x + a.y*b0.y + a.z*b0.z + a.w*b0.w;
            acc1 += a.x*b1.x + a.y*b1.y + a.z*b1.z + a.w*b1.w;
            acc2 += a.x*b2.x + a.y*b2.y + a.z*b2.z + a.w*b2.w;
        }
        #pragma unroll
        for (int o = 16; o; o >>= 1) {
            acc0 += __shfl_xor_sync(0xffffffffu, acc0, o);
            acc1 += __shfl_xor_sync(0xffffffffu, acc1, o);
            acc2 += __shfl_xor_sync(0xffffffffu, acc2, o);
        }
        if (lane == 0) {
            logits_s[j0] = acc0;
            logits_s[j1] = acc1;
            if (h2) logits_s[j2] = acc2;
        }
    }
    __syncthreads();

    // Warp 0: parallel logsumexp over 33 logits + grid reduction.
    if (warp == 0) {
        float v = logits_s[lane] * INV_T;
        float e = logits_s[NEG_K] * INV_T;
        float m = (lane == 0) ? fmaxf(v, e) : v;
        #pragma unroll
        for (int o = 16; o; o >>= 1) m = fmaxf(m, __shfl_xor_sync(0xffffffffu, m, o));
        float sse = __expf(v - m);
        if (lane == 0) sse += __expf(e - m);
        #pragma unroll
        for (int o = 16; o; o >>= 1) sse += __shfl_xor_sync(0xffffffffu, sse, o);

        if (lane == 0) {
            float rowloss = (m + logf(sse)) - logits_s[0] * INV_T;
            atomicAdd(&g_sum, rowloss);
            __threadfence();
            int done = atomicAdd(&g_count, 1);
            if (done == loss_size - 1) {
                float total = atomicExch(&g_sum, 0.0f);   // reset for graph replay
                g_count = 0;
                out[0] = (total + (float)valid * logf((float)(NEG_K + 1))) / (float)B;
            }
        }
    }
}

// ---------------- generic fallback (any H), LDG-based ----------------
__global__ __launch_bounds__(256) void infonce_generic_kernel(
    const float* __restrict__ hs, const int* __restrict__ selection,
    const int* __restrict__ mask, const float* __restrict__ noise,
    float* __restrict__ out, int B, int S, int H, int valid, int loss_size)
{
    const int l    = blockIdx.x;
    const int tid  = threadIdx.x;
    const int lane = tid & 31;
    const int warp = tid >> 5;

    __shared__ float logits_s[NSTREAMS];
    __shared__ int   cand_s[NEG_K];

    const int sel = __ldg(selection + l);
    if (warp == 0) {
        float nz = __ldg(noise + (size_t)l * NEG_K + lane);
        int msum = 0;
        const int* mrow = mask + (size_t)l * S;
        for (int s = lane; s < S; s += 32) msum += mrow[s];
        #pragma unroll
        for (int o = 16; o; o >>= 1) msum += __shfl_xor_sync(0xffffffffu, msum, o);
        const int len_l = msum;
        const bool sir = (sel >= 1) && (sel <= len_l - 1);
        const int n_valid = sir ? (len_l - 2) : (len_l - 1);
        int cand = (int)floorf(nz * (float)n_valid) + 1;
        if (sir && cand >= sel) cand += 1;
        cand_s[lane] = cand;
    }
    __syncthreads();

    const float* a = hs + ((size_t)l * S + sel) * H;
    for (int j = warp; j <= NEG_K; j += blockDim.x >> 5) {
        const float* v = (j == 0)
            ? hs + ((size_t)(valid + l) * S + sel) * H
            : hs + ((size_t)l * S + cand_s[j - 1]) * H;
        float acc = 0.0f;
        for (int i = lane; i < H; i += 32) acc += a[i] * v[i];
        #pragma unroll
        for (int o = 16; o; o >>= 1) acc += __shfl_xor_sync(0xffffffffu, acc, o);
        if (lane == 0) logits_s[j] = acc;
    }
    __syncthreads();

    if (tid == 0) {
        float m = -INFINITY;
        for (int j = 0; j <= NEG_K; j++) m = fmaxf(m, logits_s[j] * INV_T);
        float sse = 0.0f;
        for (int j = 0; j <= NEG_K; j++) sse += __expf(logits_s[j] * INV_T - m);
        float rowloss = (m + logf(sse)) - logits_s[0] * INV_T;
        atomicAdd(&g_sum, rowloss);
        __threadfence();
        int done = atomicAdd(&g_count, 1);
        if (done == loss_size - 1) {
            float total = atomicExch(&g_sum, 0.0f);
            g_count = 0;
            out[0] = (total + (float)valid * logf((float)(NEG_K + 1))) / (float)B;
        }
    }
}

extern "C" void kernel_launch(void* const* d_in, const int* in_sizes, int n_in,
                              void* d_out, int out_size) {
    const float* hs        = (const float*)d_in[0]; // [B,S,H]
    const int*   selection = (const int*)  d_in[1]; // [B]
    const int*   mask      = (const int*)  d_in[2]; // [B,S]
    const float* noise     = (const float*)d_in[3]; // [loss_size, NEG_K]
    float*       out       = (float*)d_out;

    const int B = in_sizes[1];
    const int S = in_sizes[2] / B;
    const int H = in_sizes[0] / (B * S);
    const int loss_size = in_sizes[3] / NEG_K;      // from noise shape (host-side)
    const int valid = B - loss_size;

    if (H == H_FIX) {
        infonce_occ_kernel<<<loss_size, NTHREADS>>>(hs, selection, mask, noise, out,
                                                    B, S, valid, loss_size);
    } else {
        infonce_generic_kernel<<<loss_size, 256>>>(hs, selection, mask, noise, out,
                                                   B, S, H, valid, loss_size);
    }
}